// round 14
// baseline (speedup 1.0000x reference)
#include <cuda_runtime.h>
#include <cuda_fp16.h>
#include <cstdint>

#define D_MODEL 512
#define RATIO   4
#define NGROUP  65536   // 262144 / 4

// Device scratch (allocation-guard safe)
__device__ __half g_ph[(size_t)NGROUP * D_MODEL];   // pooled, fp16
__device__ __half g_wh[D_MODEL * D_MODEL];          // W, fp16

// ---------------------------------------------------------------------------
// Kernel 1: attention pooling -> fp16 (one warp per group of 4 rows), with
// the W->fp16 conversion folded into blocks 0..255 (one float4 per thread).
// ---------------------------------------------------------------------------
__global__ __launch_bounds__(256, 5) void pool_kernel(
    const float* __restrict__ chunk,
    const float* __restrict__ query,
    const float* __restrict__ W)
{
    __shared__ __align__(16) char xsm[32768];   // 8 warps x 4 rows x 1KB
    const int tid  = threadIdx.x;
    const int lane = tid & 31;
    const int wid  = tid >> 5;
    const int gw   = blockIdx.x * 8 + wid;

    if (blockIdx.x < 256) {
        int i = blockIdx.x * 256 + tid;
        float4 v = ((const float4*)W)[i];
        __half2 h01 = __floats2half2_rn(v.x, v.y);
        __half2 h23 = __floats2half2_rn(v.z, v.w);
        uint2 u;
        u.x = *reinterpret_cast<uint32_t*>(&h01);
        u.y = *reinterpret_cast<uint32_t*>(&h23);
        ((uint2*)g_wh)[i] = u;
    }

    const float4* q4 = (const float4*)query;
    float4 q[4];
#pragma unroll
    for (int i = 0; i < 4; i++) q[i] = q4[lane + 32 * i];

    const float4* base = (const float4*)(chunk + (size_t)gw * RATIO * D_MODEL);
    char* sm = xsm + wid * 4096;

    float s[RATIO];
#pragma unroll
    for (int r = 0; r < RATIO; r++) {
        float acc = 0.f;
#pragma unroll
        for (int i = 0; i < 4; i++) {
            float4 v = base[r * (D_MODEL / 4) + lane + 32 * i];
            acc += v.x * q[i].x + v.y * q[i].y + v.z * q[i].z + v.w * q[i].w;
            __half2 h01 = __floats2half2_rn(v.x, v.y);
            __half2 h23 = __floats2half2_rn(v.z, v.w);
            uint2 u;
            u.x = *reinterpret_cast<uint32_t*>(&h01);
            u.y = *reinterpret_cast<uint32_t*>(&h23);
            *(uint2*)(sm + r * 1024 + 8 * (lane + 32 * i)) = u;  // lane-private
        }
#pragma unroll
        for (int off = 16; off; off >>= 1)
            acc += __shfl_xor_sync(0xffffffffu, acc, off);
        s[r] = acc * 0.04419417382415922f;  // 1/sqrt(512)
    }

    float m = fmaxf(fmaxf(s[0], s[1]), fmaxf(s[2], s[3]));
    float wgt[RATIO], denom = 0.f;
#pragma unroll
    for (int r = 0; r < RATIO; r++) { wgt[r] = expf(s[r] - m); denom += wgt[r]; }
    float inv = 1.f / denom;
#pragma unroll
    for (int r = 0; r < RATIO; r++) wgt[r] *= inv;

    uint2* outp = (uint2*)(g_ph + (size_t)gw * D_MODEL);
#pragma unroll
    for (int i = 0; i < 4; i++) {
        int c = lane + 32 * i;
        float2 a0 = {0.f, 0.f}, a1 = {0.f, 0.f};
#pragma unroll
        for (int r = 0; r < RATIO; r++) {
            uint2 u = *(uint2*)(sm + r * 1024 + 8 * c);
            __half2 h01 = *reinterpret_cast<__half2*>(&u.x);
            __half2 h23 = *reinterpret_cast<__half2*>(&u.y);
            float2 f0 = __half22float2(h01);
            float2 f1 = __half22float2(h23);
            a0.x += wgt[r] * f0.x;  a0.y += wgt[r] * f0.y;
            a1.x += wgt[r] * f1.x;  a1.y += wgt[r] * f1.y;
        }
        __half2 o01 = __floats2half2_rn(a0.x, a0.y);
        __half2 o23 = __floats2half2_rn(a1.x, a1.y);
        uint2 u;
        u.x = *reinterpret_cast<uint32_t*>(&o01);
        u.y = *reinterpret_cast<uint32_t*>(&o23);
        outp[c] = u;
    }
}

// ---------------------------------------------------------------------------
// Kernel 2: fp16 mma.sync GEMM.  out = pooled @ W^T + b
// BM=64, BN=128, BK=32, 256 threads (8 warps, 2m x 4n), warp tile 32x32.
// 3-stage cp.async pipeline, 45KB smem, ~80 regs -> 3 CTAs/SM (24 warps).
// ROW_BYTES=80: 16B-aligned (fixes R13 misalignment) and conflict-free
// ldmatrix (20i mod 32 distinct for i=0..7).
// ---------------------------------------------------------------------------
#define BK          32
#define ROW_BYTES   80              // 64B data + 16B pad
#define A_TILE      5120            // 64 * 80
#define B_TILE      10240           // 128 * 80
#define STAGE_BYTES (A_TILE + B_TILE)        // 15360
#define NSTAGE      3
#define SMEM_TOTAL  (NSTAGE * STAGE_BYTES)   // 46080
#define KITER       16              // 512 / 32

__device__ __forceinline__ uint32_t smem_u32(const void* p) {
    uint32_t a;
    asm("{ .reg .u64 t; cvta.to.shared.u64 t, %1; cvt.u32.u64 %0, t; }"
        : "=r"(a) : "l"(p));
    return a;
}

#define LDSM4(r0, r1, r2, r3, addr) \
    asm volatile("ldmatrix.sync.aligned.m8n8.x4.shared.b16 {%0,%1,%2,%3}, [%4];" \
                 : "=r"(r0), "=r"(r1), "=r"(r2), "=r"(r3) : "r"(addr))

#define MMA16816(c, a0, a1, a2, a3, b0, b1) \
    asm volatile("mma.sync.aligned.m16n8k16.row.col.f32.f16.f16.f32 " \
                 "{%0,%1,%2,%3}, {%4,%5,%6,%7}, {%8,%9}, {%0,%1,%2,%3};" \
                 : "+f"((c)[0]), "+f"((c)[1]), "+f"((c)[2]), "+f"((c)[3]) \
                 : "r"(a0), "r"(a1), "r"(a2), "r"(a3), "r"(b0), "r"(b1))

__device__ __forceinline__ void load_stage(uint32_t sb, int s, size_t m0, int n0)
{
    const int k0 = s * BK;
    uint32_t base = sb + (uint32_t)((s % NSTAGE) * STAGE_BYTES);
    int tid = threadIdx.x;
    // A: 64 rows x 4 chunks(16B) = 256 -> 1 per thread
    {
        int row = tid >> 2, ch = tid & 3;
        uint32_t sa = base + row * ROW_BYTES + ch * 16;
        const __half* ga = g_ph + (m0 + row) * D_MODEL + k0 + ch * 8;
        asm volatile("cp.async.cg.shared.global [%0], [%1], 16;" :: "r"(sa), "l"(ga));
    }
    // B: 128 rows x 4 chunks(16B) = 512 -> 2 per thread
#pragma unroll
    for (int i = 0; i < 2; i++) {
        int idx = tid + i * 256;
        int row = idx >> 2, ch = idx & 3;
        uint32_t sbb = base + A_TILE + row * ROW_BYTES + ch * 16;
        const __half* gb = g_wh + (size_t)(n0 + row) * D_MODEL + k0 + ch * 8;
        asm volatile("cp.async.cg.shared.global [%0], [%1], 16;" :: "r"(sbb), "l"(gb));
    }
    asm volatile("cp.async.commit_group;" ::: "memory");
}

__global__ __launch_bounds__(256, 3) void gemm_kernel(
    const float* __restrict__ bias,
    float* __restrict__ out)
{
    extern __shared__ char smem[];
    uint32_t sb = smem_u32(smem);
    const int tid  = threadIdx.x;
    const int lane = tid & 31;
    const int wid  = tid >> 5;
    const int wm   = wid & 1;       // 0..1: 32-row half
    const int wn   = wid >> 1;      // 0..3: 32-col slice
    const size_t m0 = (size_t)blockIdx.x * 64;
    const int    n0 = blockIdx.y * 128;

    float acc[2][4][4];
#pragma unroll
    for (int a = 0; a < 2; a++)
#pragma unroll
        for (int b = 0; b < 4; b++)
#pragma unroll
            for (int c = 0; c < 4; c++) acc[a][b][c] = 0.f;

    load_stage(sb, 0, m0, n0);
    load_stage(sb, 1, m0, n0);

    const int rowsel = lane & 15;
    const int ksel   = (lane >> 4) * 16;   // bytes: 8 halfs

    for (int s = 0; s < KITER; s++) {
        // allowance 1 mid-loop, 0 on the final stage
        if (s == KITER - 1)
            asm volatile("cp.async.wait_group 0;" ::: "memory");
        else
            asm volatile("cp.async.wait_group 1;" ::: "memory");
        __syncthreads();
        uint32_t base = sb + (uint32_t)((s % NSTAGE) * STAGE_BYTES);
        uint32_t abase = base + (wm * 32 + rowsel) * ROW_BYTES + ksel;
        uint32_t bbase = base + A_TILE + (wn * 32 + rowsel) * ROW_BYTES + ksel;
#pragma unroll
        for (int kk = 0; kk < 2; kk++) {
            uint32_t a[2][4], b[2][4];
#pragma unroll
            for (int mf = 0; mf < 2; mf++)
                LDSM4(a[mf][0], a[mf][1], a[mf][2], a[mf][3],
                      abase + mf * (16 * ROW_BYTES) + kk * 32);
#pragma unroll
            for (int p = 0; p < 2; p++)
                LDSM4(b[p][0], b[p][1], b[p][2], b[p][3],
                      bbase + p * (16 * ROW_BYTES) + kk * 32);
#pragma unroll
            for (int mf = 0; mf < 2; mf++)
#pragma unroll
                for (int nf = 0; nf < 4; nf++) {
                    int p = nf >> 1, q = nf & 1;
                    MMA16816(acc[mf][nf], a[mf][0], a[mf][1], a[mf][2], a[mf][3],
                             b[p][q], b[p][q + 2]);
                }
        }
        if (s + 2 < KITER) load_stage(sb, s + 2, m0, n0);
    }

    // Epilogue: direct gmem stores + bias
    float2 bv[4];
#pragma unroll
    for (int nf = 0; nf < 4; nf++) {
        int c = n0 + wn * 32 + nf * 8 + (lane & 3) * 2;
        bv[nf] = *(const float2*)(bias + c);
    }
#pragma unroll
    for (int mf = 0; mf < 2; mf++) {
        size_t r = m0 + wm * 32 + mf * 16 + (lane >> 2);
#pragma unroll
        for (int nf = 0; nf < 4; nf++) {
            int c = n0 + wn * 32 + nf * 8 + (lane & 3) * 2;
            float2 o0, o1;
            o0.x = acc[mf][nf][0] + bv[nf].x;
            o0.y = acc[mf][nf][1] + bv[nf].y;
            o1.x = acc[mf][nf][2] + bv[nf].x;
            o1.y = acc[mf][nf][3] + bv[nf].y;
            *(float2*)(out + r * D_MODEL + c)       = o0;
            *(float2*)(out + (r + 8) * D_MODEL + c) = o1;
        }
    }
}

// ---------------------------------------------------------------------------
extern "C" void kernel_launch(void* const* d_in, const int* in_sizes, int n_in,
                              void* d_out, int out_size)
{
    const float* chunk = (const float*)d_in[0];
    const float* query = (const float*)d_in[1];
    const float* w     = (const float*)d_in[2];
    const float* b     = (const float*)d_in[3];
    float*       out   = (float*)d_out;

    cudaFuncSetAttribute(gemm_kernel,
                         cudaFuncAttributeMaxDynamicSharedMemorySize, SMEM_TOTAL);

    pool_kernel<<<NGROUP / 8, 256>>>(chunk, query, w);
    dim3 grid(NGROUP / 64, D_MODEL / 128);   // (1024, 4)
    gemm_kernel<<<grid, 256, SMEM_TOTAL>>>(b, out);
}

// round 15
// speedup vs baseline: 1.1263x; 1.1263x over previous
#include <cuda_runtime.h>
#include <cuda_fp16.h>
#include <cstdint>

#define D_MODEL 512
#define RATIO   4
#define NGROUP  65536   // 262144 / 4

// Device scratch (allocation-guard safe)
__device__ __half g_ph[(size_t)NGROUP * D_MODEL];   // pooled, fp16
__device__ __half g_wh[D_MODEL * D_MODEL];          // W, fp16

// ---------------------------------------------------------------------------
// Kernel 1: attention pooling -> fp16 (one warp per group of 4 rows), with
// W->fp16 conversion folded into blocks 0..255.
// Phase-split: ALL 16 row-loads issue before any shuffle reduction -> MLP 16.
// ---------------------------------------------------------------------------
__global__ __launch_bounds__(256, 4) void pool_kernel(
    const float* __restrict__ chunk,
    const float* __restrict__ query,
    const float* __restrict__ W)
{
    __shared__ __align__(16) char xsm[32768];   // 8 warps x 4 rows x 1KB
    const int tid  = threadIdx.x;
    const int lane = tid & 31;
    const int wid  = tid >> 5;
    const int gw   = blockIdx.x * 8 + wid;

    if (blockIdx.x < 256) {
        int i = blockIdx.x * 256 + tid;
        float4 v = ((const float4*)W)[i];
        __half2 h01 = __floats2half2_rn(v.x, v.y);
        __half2 h23 = __floats2half2_rn(v.z, v.w);
        uint2 u;
        u.x = *reinterpret_cast<uint32_t*>(&h01);
        u.y = *reinterpret_cast<uint32_t*>(&h23);
        ((uint2*)g_wh)[i] = u;
    }

    const float4* q4 = (const float4*)query;
    float4 q[4];
#pragma unroll
    for (int i = 0; i < 4; i++) q[i] = q4[lane + 32 * i];

    const float4* base = (const float4*)(chunk + (size_t)gw * RATIO * D_MODEL);
    char* sm = xsm + wid * 4096;

    // Phase 1: 16 independent loads, accumulate per-row partial dots,
    // stash fp16 copies in lane-private smem. NO shuffles here.
    float pacc[RATIO] = {0.f, 0.f, 0.f, 0.f};
#pragma unroll
    for (int r = 0; r < RATIO; r++) {
#pragma unroll
        for (int i = 0; i < 4; i++) {
            float4 v = base[r * (D_MODEL / 4) + lane + 32 * i];
            pacc[r] += v.x * q[i].x + v.y * q[i].y + v.z * q[i].z + v.w * q[i].w;
            __half2 h01 = __floats2half2_rn(v.x, v.y);
            __half2 h23 = __floats2half2_rn(v.z, v.w);
            uint2 u;
            u.x = *reinterpret_cast<uint32_t*>(&h01);
            u.y = *reinterpret_cast<uint32_t*>(&h23);
            *(uint2*)(sm + r * 1024 + 8 * (lane + 32 * i)) = u;  // lane-private
        }
    }

    // Phase 2: four independent shuffle reductions (interleaved by compiler).
    float s[RATIO];
#pragma unroll
    for (int r = 0; r < RATIO; r++) {
        float acc = pacc[r];
#pragma unroll
        for (int off = 16; off; off >>= 1)
            acc += __shfl_xor_sync(0xffffffffu, acc, off);
        s[r] = acc * 0.04419417382415922f;  // 1/sqrt(512)
    }

    float m = fmaxf(fmaxf(s[0], s[1]), fmaxf(s[2], s[3]));
    float wgt[RATIO], denom = 0.f;
#pragma unroll
    for (int r = 0; r < RATIO; r++) { wgt[r] = expf(s[r] - m); denom += wgt[r]; }
    float inv = 1.f / denom;
#pragma unroll
    for (int r = 0; r < RATIO; r++) wgt[r] *= inv;

    uint2* outp = (uint2*)(g_ph + (size_t)gw * D_MODEL);
#pragma unroll
    for (int i = 0; i < 4; i++) {
        int c = lane + 32 * i;
        float2 a0 = {0.f, 0.f}, a1 = {0.f, 0.f};
#pragma unroll
        for (int r = 0; r < RATIO; r++) {
            uint2 u = *(uint2*)(sm + r * 1024 + 8 * c);
            __half2 h01 = *reinterpret_cast<__half2*>(&u.x);
            __half2 h23 = *reinterpret_cast<__half2*>(&u.y);
            float2 f0 = __half22float2(h01);
            float2 f1 = __half22float2(h23);
            a0.x += wgt[r] * f0.x;  a0.y += wgt[r] * f0.y;
            a1.x += wgt[r] * f1.x;  a1.y += wgt[r] * f1.y;
        }
        __half2 o01 = __floats2half2_rn(a0.x, a0.y);
        __half2 o23 = __floats2half2_rn(a1.x, a1.y);
        uint2 u;
        u.x = *reinterpret_cast<uint32_t*>(&o01);
        u.y = *reinterpret_cast<uint32_t*>(&o23);
        outp[c] = u;
    }
}

// ---------------------------------------------------------------------------
// Kernel 2: fp16 mma.sync GEMM -- R11 config EXACTLY (local optimum: R12's
// 16-warp CTA and R14's 32x32 warp tile both regressed ~18us).
// BM=128, BN=128, BK=64, 256 threads (8 warps, 2m x 4n), warp tile 64x32.
// 3-stage cp.async pipeline, 110.6KB smem, 2 CTAs/SM.
// ---------------------------------------------------------------------------
#define BK          64
#define ROW_BYTES   144
#define TILE_BYTES  18432           // 128 * 144
#define STAGE_BYTES 36864           // A tile + B tile
#define NSTAGE      3
#define SMEM_TOTAL  (NSTAGE * STAGE_BYTES)   // 110592
#define KITER       8               // 512 / 64

__device__ __forceinline__ uint32_t smem_u32(const void* p) {
    uint32_t a;
    asm("{ .reg .u64 t; cvta.to.shared.u64 t, %1; cvt.u32.u64 %0, t; }"
        : "=r"(a) : "l"(p));
    return a;
}

#define LDSM4(r0, r1, r2, r3, addr) \
    asm volatile("ldmatrix.sync.aligned.m8n8.x4.shared.b16 {%0,%1,%2,%3}, [%4];" \
                 : "=r"(r0), "=r"(r1), "=r"(r2), "=r"(r3) : "r"(addr))

#define MMA16816(c, a0, a1, a2, a3, b0, b1) \
    asm volatile("mma.sync.aligned.m16n8k16.row.col.f32.f16.f16.f32 " \
                 "{%0,%1,%2,%3}, {%4,%5,%6,%7}, {%8,%9}, {%0,%1,%2,%3};" \
                 : "+f"((c)[0]), "+f"((c)[1]), "+f"((c)[2]), "+f"((c)[3]) \
                 : "r"(a0), "r"(a1), "r"(a2), "r"(a3), "r"(b0), "r"(b1))

__device__ __forceinline__ void load_stage(uint32_t sb, int s, size_t m0, int n0)
{
    const int k0 = s * BK;
    uint32_t base = sb + (uint32_t)((s % NSTAGE) * STAGE_BYTES);
    int tid = threadIdx.x;
#pragma unroll
    for (int i = 0; i < 4; i++) {
        int idx = tid + i * 256;                 // 0..1023
        int row = idx >> 3, ch = idx & 7;
        uint32_t sa = base + row * ROW_BYTES + ch * 16;
        const __half* ga = g_ph + (m0 + row) * D_MODEL + k0 + ch * 8;
        asm volatile("cp.async.cg.shared.global [%0], [%1], 16;" :: "r"(sa), "l"(ga));
    }
#pragma unroll
    for (int i = 0; i < 4; i++) {
        int idx = tid + i * 256;
        int row = idx >> 3, ch = idx & 7;
        uint32_t sbb = base + TILE_BYTES + row * ROW_BYTES + ch * 16;
        const __half* gb = g_wh + (size_t)(n0 + row) * D_MODEL + k0 + ch * 8;
        asm volatile("cp.async.cg.shared.global [%0], [%1], 16;" :: "r"(sbb), "l"(gb));
    }
    asm volatile("cp.async.commit_group;" ::: "memory");
}

__global__ __launch_bounds__(256, 2) void gemm_kernel(
    const float* __restrict__ bias,
    float* __restrict__ out)
{
    extern __shared__ char smem[];
    uint32_t sb = smem_u32(smem);
    const int tid  = threadIdx.x;
    const int lane = tid & 31;
    const int wid  = tid >> 5;
    const int wm   = wid & 1;       // 0..1: 64-row half
    const int wn   = wid >> 1;      // 0..3: 32-col slice
    const size_t m0 = (size_t)blockIdx.x * 128;
    const int    n0 = blockIdx.y * 128;

    float acc[4][4][4];
#pragma unroll
    for (int a = 0; a < 4; a++)
#pragma unroll
        for (int b = 0; b < 4; b++)
#pragma unroll
            for (int c = 0; c < 4; c++) acc[a][b][c] = 0.f;

    load_stage(sb, 0, m0, n0);
    load_stage(sb, 1, m0, n0);

    const int rowsel = lane & 15;
    const int ksel   = (lane >> 4) * 16;   // bytes: 8 halfs

    for (int s = 0; s < KITER; s++) {
        // allowance 1 mid-loop, 0 on the final stage (R4 race fix)
        if (s == KITER - 1)
            asm volatile("cp.async.wait_group 0;" ::: "memory");
        else
            asm volatile("cp.async.wait_group 1;" ::: "memory");
        __syncthreads();
        uint32_t base = sb + (uint32_t)((s % NSTAGE) * STAGE_BYTES);
        uint32_t abase = base + (wm * 64 + rowsel) * ROW_BYTES + ksel;
        uint32_t bbase = base + TILE_BYTES + (wn * 32 + rowsel) * ROW_BYTES + ksel;
#pragma unroll
        for (int kk = 0; kk < 4; kk++) {
            uint32_t a[4][4], b[2][4];
#pragma unroll
            for (int mf = 0; mf < 4; mf++)
                LDSM4(a[mf][0], a[mf][1], a[mf][2], a[mf][3],
                      abase + mf * (16 * ROW_BYTES) + kk * 32);
#pragma unroll
            for (int p = 0; p < 2; p++)
                LDSM4(b[p][0], b[p][1], b[p][2], b[p][3],
                      bbase + p * (16 * ROW_BYTES) + kk * 32);
#pragma unroll
            for (int mf = 0; mf < 4; mf++)
#pragma unroll
                for (int nf = 0; nf < 4; nf++) {
                    int p = nf >> 1, q = nf & 1;
                    MMA16816(acc[mf][nf], a[mf][0], a[mf][1], a[mf][2], a[mf][3],
                             b[p][q], b[p][q + 2]);
                }
        }
        if (s + 2 < KITER) load_stage(sb, s + 2, m0, n0);
    }

    // Epilogue: direct gmem stores + bias
    float2 bv[4];
#pragma unroll
    for (int nf = 0; nf < 4; nf++) {
        int c = n0 + wn * 32 + nf * 8 + (lane & 3) * 2;
        bv[nf] = *(const float2*)(bias + c);
    }
#pragma unroll
    for (int mf = 0; mf < 4; mf++) {
        size_t r = m0 + wm * 64 + mf * 16 + (lane >> 2);
#pragma unroll
        for (int nf = 0; nf < 4; nf++) {
            int c = n0 + wn * 32 + nf * 8 + (lane & 3) * 2;
            float2 o0, o1;
            o0.x = acc[mf][nf][0] + bv[nf].x;
            o0.y = acc[mf][nf][1] + bv[nf].y;
            o1.x = acc[mf][nf][2] + bv[nf].x;
            o1.y = acc[mf][nf][3] + bv[nf].y;
            *(float2*)(out + r * D_MODEL + c)       = o0;
            *(float2*)(out + (r + 8) * D_MODEL + c) = o1;
        }
    }
}

// ---------------------------------------------------------------------------
extern "C" void kernel_launch(void* const* d_in, const int* in_sizes, int n_in,
                              void* d_out, int out_size)
{
    const float* chunk = (const float*)d_in[0];
    const float* query = (const float*)d_in[1];
    const float* w     = (const float*)d_in[2];
    const float* b     = (const float*)d_in[3];
    float*       out   = (float*)d_out;

    cudaFuncSetAttribute(gemm_kernel,
                         cudaFuncAttributeMaxDynamicSharedMemorySize, SMEM_TOTAL);

    pool_kernel<<<NGROUP / 8, 256>>>(chunk, query, w);
    dim3 grid(NGROUP / 128, D_MODEL / 128);   // (512, 4)
    gemm_kernel<<<grid, 256, SMEM_TOTAL>>>(b, out);
}

// round 16
// speedup vs baseline: 1.1321x; 1.0051x over previous
#include <cuda_runtime.h>
#include <cuda_fp16.h>
#include <cstdint>

#define D_MODEL 512
#define RATIO   4
#define NGROUP  65536   // 262144 / 4

// Device scratch (allocation-guard safe)
__device__ __half g_ph[(size_t)NGROUP * D_MODEL];   // pooled, fp16
__device__ __half g_wh[D_MODEL * D_MODEL];          // W, fp16

// ---------------------------------------------------------------------------
// Kernel 1: attention pooling -> fp16 (one warp per group of 4 rows), with
// W->fp16 conversion folded into blocks 0..255.
// Phase-split loads (MLP 16) + row cache in REGISTERS as packed half2
// (16 uint2 = 32 regs) -- no smem stash, no STS/LDS on the LSU path.
// ---------------------------------------------------------------------------
__global__ __launch_bounds__(256, 3) void pool_kernel(
    const float* __restrict__ chunk,
    const float* __restrict__ query,
    const float* __restrict__ W)
{
    const int tid  = threadIdx.x;
    const int lane = tid & 31;
    const int wid  = tid >> 5;
    const int gw   = blockIdx.x * 8 + wid;

    if (blockIdx.x < 256) {
        int i = blockIdx.x * 256 + tid;
        float4 v = ((const float4*)W)[i];
        __half2 h01 = __floats2half2_rn(v.x, v.y);
        __half2 h23 = __floats2half2_rn(v.z, v.w);
        uint2 u;
        u.x = *reinterpret_cast<uint32_t*>(&h01);
        u.y = *reinterpret_cast<uint32_t*>(&h23);
        ((uint2*)g_wh)[i] = u;
    }

    const float4* q4 = (const float4*)query;
    float4 q[4];
#pragma unroll
    for (int i = 0; i < 4; i++) q[i] = q4[lane + 32 * i];

    const float4* base = (const float4*)(chunk + (size_t)gw * RATIO * D_MODEL);

    // Phase 1: 16 independent loads; accumulate per-row partial dots;
    // pack fp16 copies into registers. No shuffles, no smem.
    uint2  xh[RATIO][4];
    float  pacc[RATIO] = {0.f, 0.f, 0.f, 0.f};
#pragma unroll
    for (int r = 0; r < RATIO; r++) {
#pragma unroll
        for (int i = 0; i < 4; i++) {
            float4 v = base[r * (D_MODEL / 4) + lane + 32 * i];
            pacc[r] += v.x * q[i].x + v.y * q[i].y + v.z * q[i].z + v.w * q[i].w;
            __half2 h01 = __floats2half2_rn(v.x, v.y);
            __half2 h23 = __floats2half2_rn(v.z, v.w);
            xh[r][i].x = *reinterpret_cast<uint32_t*>(&h01);
            xh[r][i].y = *reinterpret_cast<uint32_t*>(&h23);
        }
    }

    // Phase 2: four independent shuffle reductions.
    float s[RATIO];
#pragma unroll
    for (int r = 0; r < RATIO; r++) {
        float acc = pacc[r];
#pragma unroll
        for (int off = 16; off; off >>= 1)
            acc += __shfl_xor_sync(0xffffffffu, acc, off);
        s[r] = acc * 0.04419417382415922f;  // 1/sqrt(512)
    }

    float m = fmaxf(fmaxf(s[0], s[1]), fmaxf(s[2], s[3]));
    float wgt[RATIO], denom = 0.f;
#pragma unroll
    for (int r = 0; r < RATIO; r++) { wgt[r] = expf(s[r] - m); denom += wgt[r]; }
    float inv = 1.f / denom;
#pragma unroll
    for (int r = 0; r < RATIO; r++) wgt[r] *= inv;

    uint2* outp = (uint2*)(g_ph + (size_t)gw * D_MODEL);
#pragma unroll
    for (int i = 0; i < 4; i++) {
        float2 a0 = {0.f, 0.f}, a1 = {0.f, 0.f};
#pragma unroll
        for (int r = 0; r < RATIO; r++) {
            __half2 h01 = *reinterpret_cast<__half2*>(&xh[r][i].x);
            __half2 h23 = *reinterpret_cast<__half2*>(&xh[r][i].y);
            float2 f0 = __half22float2(h01);
            float2 f1 = __half22float2(h23);
            a0.x += wgt[r] * f0.x;  a0.y += wgt[r] * f0.y;
            a1.x += wgt[r] * f1.x;  a1.y += wgt[r] * f1.y;
        }
        __half2 o01 = __floats2half2_rn(a0.x, a0.y);
        __half2 o23 = __floats2half2_rn(a1.x, a1.y);
        uint2 u;
        u.x = *reinterpret_cast<uint32_t*>(&o01);
        u.y = *reinterpret_cast<uint32_t*>(&o23);
        outp[lane + 32 * i] = u;
    }
}

// ---------------------------------------------------------------------------
// Kernel 2: fp16 mma.sync GEMM -- FROZEN at the R11/R15 local optimum.
// BM=128, BN=128, BK=64, 256 threads (8 warps, 2m x 4n), warp tile 64x32.
// 3-stage cp.async pipeline, 110.6KB smem, 2 CTAs/SM.
// ---------------------------------------------------------------------------
#define BK          64
#define ROW_BYTES   144
#define TILE_BYTES  18432           // 128 * 144
#define STAGE_BYTES 36864           // A tile + B tile
#define NSTAGE      3
#define SMEM_TOTAL  (NSTAGE * STAGE_BYTES)   // 110592
#define KITER       8               // 512 / 64

__device__ __forceinline__ uint32_t smem_u32(const void* p) {
    uint32_t a;
    asm("{ .reg .u64 t; cvta.to.shared.u64 t, %1; cvt.u32.u64 %0, t; }"
        : "=r"(a) : "l"(p));
    return a;
}

#define LDSM4(r0, r1, r2, r3, addr) \
    asm volatile("ldmatrix.sync.aligned.m8n8.x4.shared.b16 {%0,%1,%2,%3}, [%4];" \
                 : "=r"(r0), "=r"(r1), "=r"(r2), "=r"(r3) : "r"(addr))

#define MMA16816(c, a0, a1, a2, a3, b0, b1) \
    asm volatile("mma.sync.aligned.m16n8k16.row.col.f32.f16.f16.f32 " \
                 "{%0,%1,%2,%3}, {%4,%5,%6,%7}, {%8,%9}, {%0,%1,%2,%3};" \
                 : "+f"((c)[0]), "+f"((c)[1]), "+f"((c)[2]), "+f"((c)[3]) \
                 : "r"(a0), "r"(a1), "r"(a2), "r"(a3), "r"(b0), "r"(b1))

__device__ __forceinline__ void load_stage(uint32_t sb, int s, size_t m0, int n0)
{
    const int k0 = s * BK;
    uint32_t base = sb + (uint32_t)((s % NSTAGE) * STAGE_BYTES);
    int tid = threadIdx.x;
#pragma unroll
    for (int i = 0; i < 4; i++) {
        int idx = tid + i * 256;                 // 0..1023
        int row = idx >> 3, ch = idx & 7;
        uint32_t sa = base + row * ROW_BYTES + ch * 16;
        const __half* ga = g_ph + (m0 + row) * D_MODEL + k0 + ch * 8;
        asm volatile("cp.async.cg.shared.global [%0], [%1], 16;" :: "r"(sa), "l"(ga));
    }
#pragma unroll
    for (int i = 0; i < 4; i++) {
        int idx = tid + i * 256;
        int row = idx >> 3, ch = idx & 7;
        uint32_t sbb = base + TILE_BYTES + row * ROW_BYTES + ch * 16;
        const __half* gb = g_wh + (size_t)(n0 + row) * D_MODEL + k0 + ch * 8;
        asm volatile("cp.async.cg.shared.global [%0], [%1], 16;" :: "r"(sbb), "l"(gb));
    }
    asm volatile("cp.async.commit_group;" ::: "memory");
}

__global__ __launch_bounds__(256, 2) void gemm_kernel(
    const float* __restrict__ bias,
    float* __restrict__ out)
{
    extern __shared__ char smem[];
    uint32_t sb = smem_u32(smem);
    const int tid  = threadIdx.x;
    const int lane = tid & 31;
    const int wid  = tid >> 5;
    const int wm   = wid & 1;       // 0..1: 64-row half
    const int wn   = wid >> 1;      // 0..3: 32-col slice
    const size_t m0 = (size_t)blockIdx.x * 128;
    const int    n0 = blockIdx.y * 128;

    float acc[4][4][4];
#pragma unroll
    for (int a = 0; a < 4; a++)
#pragma unroll
        for (int b = 0; b < 4; b++)
#pragma unroll
            for (int c = 0; c < 4; c++) acc[a][b][c] = 0.f;

    load_stage(sb, 0, m0, n0);
    load_stage(sb, 1, m0, n0);

    const int rowsel = lane & 15;
    const int ksel   = (lane >> 4) * 16;   // bytes: 8 halfs

    for (int s = 0; s < KITER; s++) {
        // allowance 1 mid-loop, 0 on the final stage (R4 race fix)
        if (s == KITER - 1)
            asm volatile("cp.async.wait_group 0;" ::: "memory");
        else
            asm volatile("cp.async.wait_group 1;" ::: "memory");
        __syncthreads();
        uint32_t base = sb + (uint32_t)((s % NSTAGE) * STAGE_BYTES);
        uint32_t abase = base + (wm * 64 + rowsel) * ROW_BYTES + ksel;
        uint32_t bbase = base + TILE_BYTES + (wn * 32 + rowsel) * ROW_BYTES + ksel;
#pragma unroll
        for (int kk = 0; kk < 4; kk++) {
            uint32_t a[4][4], b[2][4];
#pragma unroll
            for (int mf = 0; mf < 4; mf++)
                LDSM4(a[mf][0], a[mf][1], a[mf][2], a[mf][3],
                      abase + mf * (16 * ROW_BYTES) + kk * 32);
#pragma unroll
            for (int p = 0; p < 2; p++)
                LDSM4(b[p][0], b[p][1], b[p][2], b[p][3],
                      bbase + p * (16 * ROW_BYTES) + kk * 32);
#pragma unroll
            for (int mf = 0; mf < 4; mf++)
#pragma unroll
                for (int nf = 0; nf < 4; nf++) {
                    int p = nf >> 1, q = nf & 1;
                    MMA16816(acc[mf][nf], a[mf][0], a[mf][1], a[mf][2], a[mf][3],
                             b[p][q], b[p][q + 2]);
                }
        }
        if (s + 2 < KITER) load_stage(sb, s + 2, m0, n0);
    }

    // Epilogue: direct gmem stores + bias
    float2 bv[4];
#pragma unroll
    for (int nf = 0; nf < 4; nf++) {
        int c = n0 + wn * 32 + nf * 8 + (lane & 3) * 2;
        bv[nf] = *(const float2*)(bias + c);
    }
#pragma unroll
    for (int mf = 0; mf < 4; mf++) {
        size_t r = m0 + wm * 64 + mf * 16 + (lane >> 2);
#pragma unroll
        for (int nf = 0; nf < 4; nf++) {
            int c = n0 + wn * 32 + nf * 8 + (lane & 3) * 2;
            float2 o0, o1;
            o0.x = acc[mf][nf][0] + bv[nf].x;
            o0.y = acc[mf][nf][1] + bv[nf].y;
            o1.x = acc[mf][nf][2] + bv[nf].x;
            o1.y = acc[mf][nf][3] + bv[nf].y;
            *(float2*)(out + r * D_MODEL + c)       = o0;
            *(float2*)(out + (r + 8) * D_MODEL + c) = o1;
        }
    }
}

// ---------------------------------------------------------------------------
extern "C" void kernel_launch(void* const* d_in, const int* in_sizes, int n_in,
                              void* d_out, int out_size)
{
    const float* chunk = (const float*)d_in[0];
    const float* query = (const float*)d_in[1];
    const float* w     = (const float*)d_in[2];
    const float* b     = (const float*)d_in[3];
    float*       out   = (float*)d_out;

    cudaFuncSetAttribute(gemm_kernel,
                         cudaFuncAttributeMaxDynamicSharedMemorySize, SMEM_TOTAL);

    pool_kernel<<<NGROUP / 8, 256>>>(chunk, query, w);
    dim3 grid(NGROUP / 128, D_MODEL / 128);   // (512, 4)
    gemm_kernel<<<grid, 256, SMEM_TOTAL>>>(b, out);
}

// round 17
// speedup vs baseline: 1.1407x; 1.0076x over previous
#include <cuda_runtime.h>
#include <cuda_fp16.h>
#include <cstdint>

#define D_MODEL 512
#define RATIO   4
#define NGROUP  65536   // 262144 / 4

// Device scratch (allocation-guard safe)
__device__ __half g_ph[(size_t)NGROUP * D_MODEL];   // pooled, fp16
__device__ __half g_wh[D_MODEL * D_MODEL];          // W, fp16

// ---------------------------------------------------------------------------
// Kernel 1: attention pooling -> fp16 (one warp per group of 4 rows), with
// W->fp16 conversion folded into blocks 0..255.
// Phase-split loads (MLP 16) + row cache in registers (16 uint2 packed half2).
// At the DRAM ceiling (~6.5 TB/s) -- frozen.
// ---------------------------------------------------------------------------
__global__ __launch_bounds__(256, 3) void pool_kernel(
    const float* __restrict__ chunk,
    const float* __restrict__ query,
    const float* __restrict__ W)
{
    const int tid  = threadIdx.x;
    const int lane = tid & 31;
    const int wid  = tid >> 5;
    const int gw   = blockIdx.x * 8 + wid;

    if (blockIdx.x < 256) {
        int i = blockIdx.x * 256 + tid;
        float4 v = ((const float4*)W)[i];
        __half2 h01 = __floats2half2_rn(v.x, v.y);
        __half2 h23 = __floats2half2_rn(v.z, v.w);
        uint2 u;
        u.x = *reinterpret_cast<uint32_t*>(&h01);
        u.y = *reinterpret_cast<uint32_t*>(&h23);
        ((uint2*)g_wh)[i] = u;
    }

    const float4* q4 = (const float4*)query;
    float4 q[4];
#pragma unroll
    for (int i = 0; i < 4; i++) q[i] = q4[lane + 32 * i];

    const float4* base = (const float4*)(chunk + (size_t)gw * RATIO * D_MODEL);

    // Phase 1: 16 independent loads; per-row partial dots; fp16 pack to regs.
    uint2  xh[RATIO][4];
    float  pacc[RATIO] = {0.f, 0.f, 0.f, 0.f};
#pragma unroll
    for (int r = 0; r < RATIO; r++) {
#pragma unroll
        for (int i = 0; i < 4; i++) {
            float4 v = base[r * (D_MODEL / 4) + lane + 32 * i];
            pacc[r] += v.x * q[i].x + v.y * q[i].y + v.z * q[i].z + v.w * q[i].w;
            __half2 h01 = __floats2half2_rn(v.x, v.y);
            __half2 h23 = __floats2half2_rn(v.z, v.w);
            xh[r][i].x = *reinterpret_cast<uint32_t*>(&h01);
            xh[r][i].y = *reinterpret_cast<uint32_t*>(&h23);
        }
    }

    // Phase 2: four independent shuffle reductions.
    float s[RATIO];
#pragma unroll
    for (int r = 0; r < RATIO; r++) {
        float acc = pacc[r];
#pragma unroll
        for (int off = 16; off; off >>= 1)
            acc += __shfl_xor_sync(0xffffffffu, acc, off);
        s[r] = acc * 0.04419417382415922f;  // 1/sqrt(512)
    }

    float m = fmaxf(fmaxf(s[0], s[1]), fmaxf(s[2], s[3]));
    float wgt[RATIO], denom = 0.f;
#pragma unroll
    for (int r = 0; r < RATIO; r++) { wgt[r] = expf(s[r] - m); denom += wgt[r]; }
    float inv = 1.f / denom;
#pragma unroll
    for (int r = 0; r < RATIO; r++) wgt[r] *= inv;

    uint2* outp = (uint2*)(g_ph + (size_t)gw * D_MODEL);
#pragma unroll
    for (int i = 0; i < 4; i++) {
        float2 a0 = {0.f, 0.f}, a1 = {0.f, 0.f};
#pragma unroll
        for (int r = 0; r < RATIO; r++) {
            __half2 h01 = *reinterpret_cast<__half2*>(&xh[r][i].x);
            __half2 h23 = *reinterpret_cast<__half2*>(&xh[r][i].y);
            float2 f0 = __half22float2(h01);
            float2 f1 = __half22float2(h23);
            a0.x += wgt[r] * f0.x;  a0.y += wgt[r] * f0.y;
            a1.x += wgt[r] * f1.x;  a1.y += wgt[r] * f1.y;
        }
        __half2 o01 = __floats2half2_rn(a0.x, a0.y);
        __half2 o23 = __floats2half2_rn(a1.x, a1.y);
        uint2 u;
        u.x = *reinterpret_cast<uint32_t*>(&o01);
        u.y = *reinterpret_cast<uint32_t*>(&o23);
        outp[lane + 32 * i] = u;
    }
}

// ---------------------------------------------------------------------------
// Kernel 2: fp16 mma.sync GEMM -- R11/R15 mainloop, with the grid RASTER
// ORDER swapped: blockIdx.x = n-block (fast axis), blockIdx.y = m-block.
// Waves now contain groups of 4 CTAs sharing one A-tile -> A served from L2
// (A DRAM traffic 256MB -> ~64MB; cp.async A latency 577 -> 234 cyc for 3/4
// of tiles).
// ---------------------------------------------------------------------------
#define BK          64
#define ROW_BYTES   144
#define TILE_BYTES  18432           // 128 * 144
#define STAGE_BYTES 36864           // A tile + B tile
#define NSTAGE      3
#define SMEM_TOTAL  (NSTAGE * STAGE_BYTES)   // 110592
#define KITER       8               // 512 / 64

__device__ __forceinline__ uint32_t smem_u32(const void* p) {
    uint32_t a;
    asm("{ .reg .u64 t; cvta.to.shared.u64 t, %1; cvt.u32.u64 %0, t; }"
        : "=r"(a) : "l"(p));
    return a;
}

#define LDSM4(r0, r1, r2, r3, addr) \
    asm volatile("ldmatrix.sync.aligned.m8n8.x4.shared.b16 {%0,%1,%2,%3}, [%4];" \
                 : "=r"(r0), "=r"(r1), "=r"(r2), "=r"(r3) : "r"(addr))

#define MMA16816(c, a0, a1, a2, a3, b0, b1) \
    asm volatile("mma.sync.aligned.m16n8k16.row.col.f32.f16.f16.f32 " \
                 "{%0,%1,%2,%3}, {%4,%5,%6,%7}, {%8,%9}, {%0,%1,%2,%3};" \
                 : "+f"((c)[0]), "+f"((c)[1]), "+f"((c)[2]), "+f"((c)[3]) \
                 : "r"(a0), "r"(a1), "r"(a2), "r"(a3), "r"(b0), "r"(b1))

__device__ __forceinline__ void load_stage(uint32_t sb, int s, size_t m0, int n0)
{
    const int k0 = s * BK;
    uint32_t base = sb + (uint32_t)((s % NSTAGE) * STAGE_BYTES);
    int tid = threadIdx.x;
#pragma unroll
    for (int i = 0; i < 4; i++) {
        int idx = tid + i * 256;                 // 0..1023
        int row = idx >> 3, ch = idx & 7;
        uint32_t sa = base + row * ROW_BYTES + ch * 16;
        const __half* ga = g_ph + (m0 + row) * D_MODEL + k0 + ch * 8;
        asm volatile("cp.async.cg.shared.global [%0], [%1], 16;" :: "r"(sa), "l"(ga));
    }
#pragma unroll
    for (int i = 0; i < 4; i++) {
        int idx = tid + i * 256;
        int row = idx >> 3, ch = idx & 7;
        uint32_t sbb = base + TILE_BYTES + row * ROW_BYTES + ch * 16;
        const __half* gb = g_wh + (size_t)(n0 + row) * D_MODEL + k0 + ch * 8;
        asm volatile("cp.async.cg.shared.global [%0], [%1], 16;" :: "r"(sbb), "l"(gb));
    }
    asm volatile("cp.async.commit_group;" ::: "memory");
}

__global__ __launch_bounds__(256, 2) void gemm_kernel(
    const float* __restrict__ bias,
    float* __restrict__ out)
{
    extern __shared__ char smem[];
    uint32_t sb = smem_u32(smem);
    const int tid  = threadIdx.x;
    const int lane = tid & 31;
    const int wid  = tid >> 5;
    const int wm   = wid & 1;       // 0..1: 64-row half
    const int wn   = wid >> 1;      // 0..3: 32-col slice
    // RASTER SWAP: x = n-block (fast), y = m-block.
    const size_t m0 = (size_t)blockIdx.y * 128;
    const int    n0 = blockIdx.x * 128;

    float acc[4][4][4];
#pragma unroll
    for (int a = 0; a < 4; a++)
#pragma unroll
        for (int b = 0; b < 4; b++)
#pragma unroll
            for (int c = 0; c < 4; c++) acc[a][b][c] = 0.f;

    load_stage(sb, 0, m0, n0);
    load_stage(sb, 1, m0, n0);

    const int rowsel = lane & 15;
    const int ksel   = (lane >> 4) * 16;   // bytes: 8 halfs

    for (int s = 0; s < KITER; s++) {
        // allowance 1 mid-loop, 0 on the final stage (R4 race fix)
        if (s == KITER - 1)
            asm volatile("cp.async.wait_group 0;" ::: "memory");
        else
            asm volatile("cp.async.wait_group 1;" ::: "memory");
        __syncthreads();
        uint32_t base = sb + (uint32_t)((s % NSTAGE) * STAGE_BYTES);
        uint32_t abase = base + (wm * 64 + rowsel) * ROW_BYTES + ksel;
        uint32_t bbase = base + TILE_BYTES + (wn * 32 + rowsel) * ROW_BYTES + ksel;
#pragma unroll
        for (int kk = 0; kk < 4; kk++) {
            uint32_t a[4][4], b[2][4];
#pragma unroll
            for (int mf = 0; mf < 4; mf++)
                LDSM4(a[mf][0], a[mf][1], a[mf][2], a[mf][3],
                      abase + mf * (16 * ROW_BYTES) + kk * 32);
#pragma unroll
            for (int p = 0; p < 2; p++)
                LDSM4(b[p][0], b[p][1], b[p][2], b[p][3],
                      bbase + p * (16 * ROW_BYTES) + kk * 32);
#pragma unroll
            for (int mf = 0; mf < 4; mf++)
#pragma unroll
                for (int nf = 0; nf < 4; nf++) {
                    int p = nf >> 1, q = nf & 1;
                    MMA16816(acc[mf][nf], a[mf][0], a[mf][1], a[mf][2], a[mf][3],
                             b[p][q], b[p][q + 2]);
                }
        }
        if (s + 2 < KITER) load_stage(sb, s + 2, m0, n0);
    }

    // Epilogue: direct gmem stores + bias
    float2 bv[4];
#pragma unroll
    for (int nf = 0; nf < 4; nf++) {
        int c = n0 + wn * 32 + nf * 8 + (lane & 3) * 2;
        bv[nf] = *(const float2*)(bias + c);
    }
#pragma unroll
    for (int mf = 0; mf < 4; mf++) {
        size_t r = m0 + wm * 64 + mf * 16 + (lane >> 2);
#pragma unroll
        for (int nf = 0; nf < 4; nf++) {
            int c = n0 + wn * 32 + nf * 8 + (lane & 3) * 2;
            float2 o0, o1;
            o0.x = acc[mf][nf][0] + bv[nf].x;
            o0.y = acc[mf][nf][1] + bv[nf].y;
            o1.x = acc[mf][nf][2] + bv[nf].x;
            o1.y = acc[mf][nf][3] + bv[nf].y;
            *(float2*)(out + r * D_MODEL + c)       = o0;
            *(float2*)(out + (r + 8) * D_MODEL + c) = o1;
        }
    }
}

// ---------------------------------------------------------------------------
extern "C" void kernel_launch(void* const* d_in, const int* in_sizes, int n_in,
                              void* d_out, int out_size)
{
    const float* chunk = (const float*)d_in[0];
    const float* query = (const float*)d_in[1];
    const float* w     = (const float*)d_in[2];
    const float* b     = (const float*)d_in[3];
    float*       out   = (float*)d_out;

    cudaFuncSetAttribute(gemm_kernel,
                         cudaFuncAttributeMaxDynamicSharedMemorySize, SMEM_TOTAL);

    pool_kernel<<<NGROUP / 8, 256>>>(chunk, query, w);
    dim3 grid(D_MODEL / 128, NGROUP / 128);   // (4, 512): n fast, m slow
    gemm_kernel<<<grid, 256, SMEM_TOTAL>>>(b, out);
}